// round 1
// baseline (speedup 1.0000x reference)
#include <cuda_runtime.h>
#include <math.h>

#define HW    3136
#define WIMG  56
#define CDIM  512
#define NH    16
#define DH    32
#define BATCH 8

// Scratch (device globals: no allocation allowed in kernel_launch)
__device__ float g_qkv[(size_t)BATCH * 3 * CDIM * HW];  // (B, 1536, 3136): q rows [0,512), k [512,1024), v [1024,1536)
__device__ float g_ctx[(size_t)BATCH * CDIM * HW];      // (B, 512, 3136) attention output, channel = head*32+dim

// ---------------------------------------------------------------------------
// GEMM: C[b] (N x 3136) = A (N x K) @ B[b] (K x 3136)
// A row-major (K contiguous), B row-major (M contiguous).
// QSCALE: multiply rows [0,512) by 1/sqrt(32)  (q scaling fused into QKV GEMM)
// BIAS:   add per-row bias (proj_b)
// ---------------------------------------------------------------------------
template<bool QSCALE, bool BIAS>
__global__ void __launch_bounds__(256) gemm128(
    const float* __restrict__ A, const float* __restrict__ B,
    float* __restrict__ C, const float* __restrict__ bias,
    int K, int N)
{
    const int M = HW;
    __shared__ float As[8][128];
    __shared__ float Bs[8][128];

    const int m0 = blockIdx.x * 128;
    const int n0 = blockIdx.y * 128;
    const int b  = blockIdx.z;

    const float* Bb = B + (size_t)b * K * M;
    float*       Cb = C + (size_t)b * N * M;

    const int tid  = threadIdx.x;
    const int arow = tid >> 1;          // 0..127
    const int acol = (tid & 1) * 4;     // 0 or 4
    const int brow = tid >> 5;          // 0..7
    const int bcol = (tid & 31) * 4;    // 0..124

    const int tr = (tid >> 4) * 8;      // N offset in tile
    const int tc = (tid & 15) * 8;      // M offset in tile

    float acc[8][8];
    #pragma unroll
    for (int i = 0; i < 8; i++)
        #pragma unroll
        for (int j = 0; j < 8; j++) acc[i][j] = 0.f;

    for (int k0 = 0; k0 < K; k0 += 8) {
        float4 av = *(const float4*)&A[(size_t)(n0 + arow) * K + k0 + acol];
        float4 bv = make_float4(0.f, 0.f, 0.f, 0.f);
        int gm = m0 + bcol;
        if (gm < M) bv = *(const float4*)&Bb[(size_t)(k0 + brow) * M + gm];

        __syncthreads();   // previous iteration's compute done
        As[acol + 0][arow] = av.x;
        As[acol + 1][arow] = av.y;
        As[acol + 2][arow] = av.z;
        As[acol + 3][arow] = av.w;
        *(float4*)&Bs[brow][bcol] = bv;
        __syncthreads();

        #pragma unroll
        for (int kk = 0; kk < 8; kk++) {
            float a[8], bb[8];
            *(float4*)(a)      = *(const float4*)&As[kk][tr];
            *(float4*)(a + 4)  = *(const float4*)&As[kk][tr + 4];
            *(float4*)(bb)     = *(const float4*)&Bs[kk][tc];
            *(float4*)(bb + 4) = *(const float4*)&Bs[kk][tc + 4];
            #pragma unroll
            for (int i = 0; i < 8; i++)
                #pragma unroll
                for (int j = 0; j < 8; j++)
                    acc[i][j] += a[i] * bb[j];
        }
    }

    #pragma unroll
    for (int i = 0; i < 8; i++) {
        const int row = n0 + tr + i;
        float scale = 1.f;
        if (QSCALE) scale = (row < 512) ? 0.17677669529663688f : 1.f;  // 1/sqrt(32)
        float bv = BIAS ? bias[row] : 0.f;
        #pragma unroll
        for (int j = 0; j < 8; j += 4) {
            int m = m0 + tc + j;
            if (m < M) {
                float4 v;
                v.x = acc[i][j + 0] * scale + bv;
                v.y = acc[i][j + 1] * scale + bv;
                v.z = acc[i][j + 2] * scale + bv;
                v.w = acc[i][j + 3] * scale + bv;
                *(float4*)&Cb[(size_t)row * M + m] = v;
            }
        }
    }
}

// ---------------------------------------------------------------------------
// Neighborhood attention, 7x7 window with boundary clipping.
// Block = (tile of 8x8 query pixels, one head, one batch). 64 threads,
// one query pixel per thread. Key/value windows are always a fixed 14x14
// patch at r0=clamp(i0-3,0,42), c0=clamp(j0-3,0,42) which provably covers
// all clipped neighborhoods of the tile. K then V staged through the same
// smem buffer (two phases) to stay under 48KB static smem.
// ---------------------------------------------------------------------------
__global__ void __launch_bounds__(64) natten_kernel(const float* __restrict__ rpb)
{
    __shared__ float kv[32][196];   // [dim][14*14]
    __shared__ float rs[169];       // rpb for this head (13*13)

    const int tile = blockIdx.x;            // 0..48
    const int head = blockIdx.y;            // 0..15
    const int b    = blockIdx.z;            // 0..7
    const int ti = tile / 7, tj = tile % 7;
    const int i0 = ti * 8,   j0 = tj * 8;
    const int r0 = min(max(i0 - 3, 0), 42);
    const int c0 = min(max(j0 - 3, 0), 42);

    const size_t base = ((size_t)b * 1536 + head * 32) * HW;
    const float* qb = g_qkv + base;
    const float* kb = qb + (size_t)512 * HW;
    const float* vb = qb + (size_t)1024 * HW;

    const int tid = threadIdx.x;

    for (int t = tid; t < 169; t += 64) rs[t] = rpb[head * 169 + t];
    for (int t = tid; t < 32 * 196; t += 64) {
        int d = t / 196, pos = t % 196;
        kv[d][pos] = kb[(size_t)d * HW + (r0 + pos / 14) * WIMG + c0 + pos % 14];
    }

    const int ty = tid >> 3, tx = tid & 7;
    const int i = i0 + ty, j = j0 + tx;
    const int si = min(max(i - 3, 0), 49);
    const int sj = min(max(j - 3, 0), 49);
    const int rbase = (si - r0) * 14 + (sj - c0);
    const int boff  = (si - i + 6) * 13 + (sj - j + 6);

    float q[32];
    #pragma unroll
    for (int d = 0; d < 32; d++) q[d] = qb[(size_t)d * HW + i * WIMG + j];

    __syncthreads();

    float logit[49];
    #pragma unroll
    for (int a = 0; a < 7; a++) {
        #pragma unroll
        for (int c = 0; c < 7; c++) {
            const int pos = rbase + a * 14 + c;
            float acc = 0.f;
            #pragma unroll
            for (int d = 0; d < 32; d++) acc += q[d] * kv[d][pos];
            logit[a * 7 + c] = acc + rs[boff + a * 13 + c];
        }
    }

    float mx = logit[0];
    #pragma unroll
    for (int t = 1; t < 49; t++) mx = fmaxf(mx, logit[t]);
    float s = 0.f;
    #pragma unroll
    for (int t = 0; t < 49; t++) { float e = __expf(logit[t] - mx); logit[t] = e; s += e; }
    const float inv = 1.f / s;

    __syncthreads();   // everyone done reading K
    for (int t = tid; t < 32 * 196; t += 64) {
        int d = t / 196, pos = t % 196;
        kv[d][pos] = vb[(size_t)d * HW + (r0 + pos / 14) * WIMG + c0 + pos % 14];
    }
    __syncthreads();

    float out[32];
    #pragma unroll
    for (int d = 0; d < 32; d++) out[d] = 0.f;
    #pragma unroll
    for (int a = 0; a < 7; a++) {
        #pragma unroll
        for (int c = 0; c < 7; c++) {
            const float w = logit[a * 7 + c];
            const int pos = rbase + a * 14 + c;
            #pragma unroll
            for (int d = 0; d < 32; d++) out[d] += w * kv[d][pos];
        }
    }

    float* ob = g_ctx + ((size_t)b * 512 + head * 32) * HW + i * WIMG + j;
    #pragma unroll
    for (int d = 0; d < 32; d++) ob[(size_t)d * HW] = out[d] * inv;
}

// ---------------------------------------------------------------------------
extern "C" void kernel_launch(void* const* d_in, const int* in_sizes, int n_in,
                              void* d_out, int out_size)
{
    (void)in_sizes; (void)n_in; (void)out_size;
    const float* x      = (const float*)d_in[0];  // (8, 512, 56, 56)
    const float* qkv_w  = (const float*)d_in[1];  // (1536, 512)
    const float* rpb    = (const float*)d_in[2];  // (16, 13, 13)
    const float* proj_w = (const float*)d_in[3];  // (512, 512)
    const float* proj_b = (const float*)d_in[4];  // (512,)
    float* out = (float*)d_out;                   // (8, 512, 56, 56)

    float *qkvp, *ctxp;
    cudaGetSymbolAddress((void**)&qkvp, g_qkv);
    cudaGetSymbolAddress((void**)&ctxp, g_ctx);

    // 1) QKV: qkv[b] = qkv_w @ x[b], q rows scaled by 1/sqrt(32)
    gemm128<true, false><<<dim3(25, 12, BATCH), 256>>>(qkv_w, x, qkvp, nullptr, 512, 1536);
    // 2) neighborhood attention
    natten_kernel<<<dim3(49, NH, BATCH), 64>>>(rpb);
    // 3) projection: out[b] = proj_w @ ctx[b] + proj_b  (already NCHW)
    gemm128<false, true><<<dim3(25, 4, BATCH), 256>>>(proj_w, ctxp, out, proj_b, 512, 512);
}

// round 6
// speedup vs baseline: 1.7609x; 1.7609x over previous
#include <cuda_runtime.h>
#include <cuda_bf16.h>
#include <cstdint>
#include <math.h>

#define HW    3136
#define WIMG  56
#define CDIM  512
#define KEXP  1536          // expanded K (hi|lo|hi)
#define NH    16
#define BATCH 8

// ---------------- device scratch (no allocation allowed) ----------------
__device__ __align__(128) float g_qkv[(size_t)BATCH * 3 * CDIM * HW];  // (B,1536,3136)
__device__ __align__(128) float g_ctx[(size_t)BATCH * CDIM * HW];      // attention out
__device__ __align__(128) __nv_bfloat16 g_xe[(size_t)BATCH * KEXP * HW];   // x expanded
__device__ __align__(128) __nv_bfloat16 g_ce[(size_t)BATCH * KEXP * HW];   // ctx expanded
__device__ __align__(128) __nv_bfloat16 g_wqkv[(size_t)3 * CDIM * KEXP];   // (1536 x 1536)
__device__ __align__(128) __nv_bfloat16 g_wproj[(size_t)CDIM * KEXP];      // (512 x 1536)

// ---------------- PTX helpers (all sm_80-baseline, no arch-specific ops) ----
__device__ __forceinline__ uint32_t smem_u32(const void* p) {
    uint32_t a;
    asm("{ .reg .u64 t; cvta.to.shared.u64 t, %1; cvt.u32.u64 %0, t; }" : "=r"(a) : "l"(p));
    return a;
}
__device__ __forceinline__ void cp16(uint32_t dst, const void* src) {
    asm volatile("cp.async.cg.shared.global [%0], [%1], 16;" :: "r"(dst), "l"(src));
}
__device__ __forceinline__ void cp16z(uint32_t dst, const void* src, bool pred) {
    int sz = pred ? 16 : 0;
    asm volatile("cp.async.cg.shared.global [%0], [%1], 16, %2;" :: "r"(dst), "l"(src), "r"(sz));
}
__device__ __forceinline__ void cp_commit() { asm volatile("cp.async.commit_group;" ::: "memory"); }
template <int N> __device__ __forceinline__ void cp_wait() { asm volatile("cp.async.wait_group %0;" :: "n"(N) : "memory"); }

#define LDSM4(r, a) \
    asm volatile("ldmatrix.sync.aligned.m8n8.x4.shared.b16 {%0,%1,%2,%3}, [%4];" \
        : "=r"((r)[0]), "=r"((r)[1]), "=r"((r)[2]), "=r"((r)[3]) : "r"(a))
#define LDSM4T(r, a) \
    asm volatile("ldmatrix.sync.aligned.m8n8.x4.trans.shared.b16 {%0,%1,%2,%3}, [%4];" \
        : "=r"((r)[0]), "=r"((r)[1]), "=r"((r)[2]), "=r"((r)[3]) : "r"(a))
#define MMA16816(d, a, b0, b1) \
    asm volatile("mma.sync.aligned.m16n8k16.row.col.f32.bf16.bf16.f32 " \
        "{%0,%1,%2,%3}, {%4,%5,%6,%7}, {%8,%9}, {%0,%1,%2,%3};" \
        : "+f"((d)[0]), "+f"((d)[1]), "+f"((d)[2]), "+f"((d)[3]) \
        : "r"((a)[0]), "r"((a)[1]), "r"((a)[2]), "r"((a)[3]), "r"(b0), "r"(b1))

// ---------------------------------------------------------------------------
// Conversion: fp32 -> split bf16, K 512 -> 1536
// X rows: [0,512)=hi [512,1024)=hi [1024,1536)=lo ; W cols: [hi | lo | hi]
// ---------------------------------------------------------------------------
__global__ void __launch_bounds__(256) expand_x(const float* __restrict__ src,
                                                __nv_bfloat16* __restrict__ dst) {
    size_t i = ((size_t)blockIdx.x * 256 + threadIdx.x) * 4;
    const size_t plane = (size_t)CDIM * HW;
    size_t b = i / plane, r = i - b * plane;
    float4 v = *(const float4*)(src + i);
    __nv_bfloat16 h0 = __float2bfloat16(v.x), h1 = __float2bfloat16(v.y);
    __nv_bfloat16 h2 = __float2bfloat16(v.z), h3 = __float2bfloat16(v.w);
    __nv_bfloat162 hA; hA.x = h0; hA.y = h1;
    __nv_bfloat162 hB; hB.x = h2; hB.y = h3;
    __nv_bfloat162 lA, lB;
    lA.x = __float2bfloat16(v.x - __bfloat162float(h0));
    lA.y = __float2bfloat16(v.y - __bfloat162float(h1));
    lB.x = __float2bfloat16(v.z - __bfloat162float(h2));
    lB.y = __float2bfloat16(v.w - __bfloat162float(h3));
    __nv_bfloat16* base = dst + b * (size_t)KEXP * HW + r;
    *(__nv_bfloat162*)(base) = hA;                      *(__nv_bfloat162*)(base + 2) = hB;
    *(__nv_bfloat162*)(base + (size_t)512 * HW) = hA;   *(__nv_bfloat162*)(base + (size_t)512 * HW + 2) = hB;
    *(__nv_bfloat162*)(base + (size_t)1024 * HW) = lA;  *(__nv_bfloat162*)(base + (size_t)1024 * HW + 2) = lB;
}

__global__ void __launch_bounds__(256) expand_w(const float* __restrict__ w,
                                                __nv_bfloat16* __restrict__ we, int qrows) {
    int i = blockIdx.x * 256 + threadIdx.x;
    int row = i >> 9, k = i & 511;
    float v = w[i];
    if (row < qrows) v *= 0.17677669529663688f;   // 1/sqrt(32) folded into W_q
    __nv_bfloat16 h = __float2bfloat16(v);
    __nv_bfloat16 l = __float2bfloat16(v - __bfloat162float(h));
    __nv_bfloat16* o = we + (size_t)row * KEXP;
    o[k] = h; o[512 + k] = l; o[1024 + k] = h;
}

// ---------------------------------------------------------------------------
// Tensor-core GEMM via mma.sync (HMMA): C[b](Nout x 3136) = A'(Nout x 1536) @ B'[b](1536 x 3136)
// 128x128 tile, K-chunk 32, 256 thr (8 warps of 32x64), cp.async double buffer.
// Smem: A padded 40 bf16/row (80B), B padded 136 bf16/row (272B) -- both
// conflict-free for ldmatrix 8-lane phases (gcd checks: 80->step20, 272->step4 banks).
// ---------------------------------------------------------------------------
#define A_STRIDE_B 80
#define B_STRIDE_B 272
#define A_STAGE (128 * A_STRIDE_B)       // 10240
#define B_STAGE (32 * B_STRIDE_B)        // 8704
#define STAGE_B (A_STAGE + B_STAGE)      // 18944
#define NCHUNK  (KEXP / 32)              // 48

template<bool BIAS>
__global__ void __launch_bounds__(256) gemm_mma(
    const __nv_bfloat16* __restrict__ A, const __nv_bfloat16* __restrict__ Bx,
    float* __restrict__ C, const float* __restrict__ bias, int Nout)
{
    __shared__ __align__(16) char smem[2 * STAGE_B];
    const int tid = threadIdx.x;
    const int wid = tid >> 5, lane = tid & 31;
    const int wm = wid >> 1, wn = wid & 1;           // warp tile: rows wm*32, cols wn*64
    const int n0 = blockIdx.x * 128;
    const int m0 = blockIdx.y * 128;
    const int b  = blockIdx.z;
    const bool full = (n0 + 128 <= HW);

    const uint32_t sb = smem_u32(smem);
    const __nv_bfloat16* Ag = A + (size_t)m0 * KEXP;
    const __nv_bfloat16* Bg = Bx + (size_t)b * KEXP * HW + n0;

    float acc[2][8][4];
    #pragma unroll
    for (int i = 0; i < 2; i++)
        #pragma unroll
        for (int j = 0; j < 8; j++)
            #pragma unroll
            for (int k = 0; k < 4; k++) acc[i][j][k] = 0.f;

    auto load = [&](int c, int s) {
        uint32_t as = sb + s * STAGE_B;
        uint32_t bs = as + A_STAGE;
        #pragma unroll
        for (int it = 0; it < 2; it++) {              // A: 128 rows x 4 chunks of 16B
            int q = tid + it * 256;
            int row = q >> 2, seg = q & 3;
            cp16(as + row * A_STRIDE_B + seg * 16,
                 Ag + (size_t)row * KEXP + c * 32 + seg * 8);
        }
        #pragma unroll
        for (int it = 0; it < 2; it++) {              // B: 32 rows x 16 chunks of 16B
            int q = tid + it * 256;
            int row = q >> 4, seg = q & 15;
            bool p = full || (seg < 8);               // last pixel tile: 64 valid cols
            const __nv_bfloat16* src = Bg + (size_t)(c * 32 + row) * HW + (p ? seg * 8 : 0);
            cp16z(bs + row * B_STRIDE_B + seg * 16, src, p);
        }
        cp_commit();
    };

    load(0, 0);
    for (int i = 0; i < NCHUNK; i++) {
        int s = i & 1;
        if (i + 1 < NCHUNK) { load(i + 1, s ^ 1); cp_wait<1>(); }
        else                { cp_wait<0>(); }
        __syncthreads();

        uint32_t as = sb + s * STAGE_B;
        uint32_t bs = as + A_STAGE;
        #pragma unroll
        for (int kk = 0; kk < 2; kk++) {
            uint32_t af[2][4], bf[4][4];
            #pragma unroll
            for (int im = 0; im < 2; im++) {
                uint32_t addr = as + (wm * 32 + im * 16 + (lane & 15)) * A_STRIDE_B
                              + kk * 32 + ((lane >> 4) << 4);
                LDSM4(af[im], addr);
            }
            #pragma unroll
            for (int jn = 0; jn < 4; jn++) {
                uint32_t addr = bs + (kk * 16 + (lane & 15)) * B_STRIDE_B
                              + (wn * 64 + jn * 16 + ((lane >> 4) << 3)) * 2;
                LDSM4T(bf[jn], addr);
            }
            #pragma unroll
            for (int im = 0; im < 2; im++)
                #pragma unroll
                for (int jn = 0; jn < 4; jn++) {
                    MMA16816(acc[im][jn * 2 + 0], af[im], bf[jn][0], bf[jn][1]);
                    MMA16816(acc[im][jn * 2 + 1], af[im], bf[jn][2], bf[jn][3]);
                }
        }
        __syncthreads();
    }

    // epilogue: fragments -> global fp32 (row-major, pixel contiguous)
    const int r0 = wm * 32 + (lane >> 2);
    const int cb = wn * 64 + (lane & 3) * 2;
    const int nvalid = full ? 128 : 64;
    #pragma unroll
    for (int im = 0; im < 2; im++) {
        int rowA = m0 + r0 + im * 16;
        float bv0 = BIAS ? bias[rowA] : 0.f;
        float bv1 = BIAS ? bias[rowA + 8] : 0.f;
        float* p0 = C + (size_t)b * Nout * HW + (size_t)rowA * HW + n0;
        float* p1 = p0 + (size_t)8 * HW;
        #pragma unroll
        for (int jn = 0; jn < 8; jn++) {
            int col = cb + jn * 8;
            if (col < nvalid) {
                float2 v0 = make_float2(acc[im][jn][0] + bv0, acc[im][jn][1] + bv0);
                float2 v1 = make_float2(acc[im][jn][2] + bv1, acc[im][jn][3] + bv1);
                *(float2*)(p0 + col) = v0;
                *(float2*)(p1 + col) = v1;
            }
        }
    }
}

// ---------------------------------------------------------------------------
// Neighborhood attention (fp32 SIMT)
// ---------------------------------------------------------------------------
__global__ void __launch_bounds__(64) natten_kernel(const float* __restrict__ rpb)
{
    __shared__ float kv[32][196];
    __shared__ float rs[169];

    const int tile = blockIdx.x, head = blockIdx.y, b = blockIdx.z;
    const int ti = tile / 7, tj = tile % 7;
    const int i0 = ti * 8,   j0 = tj * 8;
    const int r0 = min(max(i0 - 3, 0), 42);
    const int c0 = min(max(j0 - 3, 0), 42);

    const size_t base = ((size_t)b * 1536 + head * 32) * HW;
    const float* qb = g_qkv + base;
    const float* kb = qb + (size_t)512 * HW;
    const float* vb = qb + (size_t)1024 * HW;
    const int tid = threadIdx.x;

    for (int t = tid; t < 169; t += 64) rs[t] = rpb[head * 169 + t];
    for (int t = tid; t < 32 * 196; t += 64) {
        int d = t / 196, pos = t % 196;
        kv[d][pos] = kb[(size_t)d * HW + (r0 + pos / 14) * WIMG + c0 + pos % 14];
    }

    const int ty = tid >> 3, tx = tid & 7;
    const int i = i0 + ty, j = j0 + tx;
    const int si = min(max(i - 3, 0), 49);
    const int sj = min(max(j - 3, 0), 49);
    const int rbase = (si - r0) * 14 + (sj - c0);
    const int boff  = (si - i + 6) * 13 + (sj - j + 6);

    float q[32];
    #pragma unroll
    for (int d = 0; d < 32; d++) q[d] = qb[(size_t)d * HW + i * WIMG + j];
    __syncthreads();

    float logit[49];
    #pragma unroll
    for (int a = 0; a < 7; a++)
        #pragma unroll
        for (int c = 0; c < 7; c++) {
            const int pos = rbase + a * 14 + c;
            float acc = 0.f;
            #pragma unroll
            for (int d = 0; d < 32; d++) acc += q[d] * kv[d][pos];
            logit[a * 7 + c] = acc + rs[boff + a * 13 + c];
        }

    float mx = logit[0];
    #pragma unroll
    for (int t = 1; t < 49; t++) mx = fmaxf(mx, logit[t]);
    float s = 0.f;
    #pragma unroll
    for (int t = 0; t < 49; t++) { float e = __expf(logit[t] - mx); logit[t] = e; s += e; }
    const float inv = 1.f / s;

    __syncthreads();
    for (int t = tid; t < 32 * 196; t += 64) {
        int d = t / 196, pos = t % 196;
        kv[d][pos] = vb[(size_t)d * HW + (r0 + pos / 14) * WIMG + c0 + pos % 14];
    }
    __syncthreads();

    float out[32];
    #pragma unroll
    for (int d = 0; d < 32; d++) out[d] = 0.f;
    #pragma unroll
    for (int a = 0; a < 7; a++)
        #pragma unroll
        for (int c = 0; c < 7; c++) {
            const float w = logit[a * 7 + c];
            const int pos = rbase + a * 14 + c;
            #pragma unroll
            for (int d = 0; d < 32; d++) out[d] += w * kv[d][pos];
        }

    float* ob = g_ctx + ((size_t)b * 512 + head * 32) * HW + i * WIMG + j;
    #pragma unroll
    for (int d = 0; d < 32; d++) ob[(size_t)d * HW] = out[d] * inv;
}

// ---------------------------------------------------------------------------
extern "C" void kernel_launch(void* const* d_in, const int* in_sizes, int n_in,
                              void* d_out, int out_size)
{
    (void)in_sizes; (void)n_in; (void)out_size;
    const float* x      = (const float*)d_in[0];
    const float* qkv_w  = (const float*)d_in[1];
    const float* rpb    = (const float*)d_in[2];
    const float* proj_w = (const float*)d_in[3];
    const float* proj_b = (const float*)d_in[4];
    float* out = (float*)d_out;

    float *qkvp, *ctxp;
    __nv_bfloat16 *xe, *ce, *wq, *wp;
    cudaGetSymbolAddress((void**)&qkvp, g_qkv);
    cudaGetSymbolAddress((void**)&ctxp, g_ctx);
    cudaGetSymbolAddress((void**)&xe, g_xe);
    cudaGetSymbolAddress((void**)&ce, g_ce);
    cudaGetSymbolAddress((void**)&wq, g_wqkv);
    cudaGetSymbolAddress((void**)&wp, g_wproj);

    // 0) precision-split conversions
    expand_w<<<(3 * CDIM * CDIM) / 256, 256>>>(qkv_w, wq, 512);
    expand_w<<<(CDIM * CDIM) / 256, 256>>>(proj_w, wp, 0);
    expand_x<<<(BATCH * CDIM * HW) / 1024, 256>>>(x, xe);

    // 1) QKV GEMM (tensor cores via mma.sync), q-scale folded into W
    gemm_mma<false><<<dim3(25, 12, BATCH), 256>>>(wq, xe, qkvp, nullptr, 1536);

    // 2) neighborhood attention
    natten_kernel<<<dim3(49, NH, BATCH), 64>>>(rpb);

    // 3) projection GEMM + bias, direct NCHW output
    expand_x<<<(BATCH * CDIM * HW) / 1024, 256>>>(ctxp, ce);
    gemm_mma<true><<<dim3(25, 4, BATCH), 256>>>(wp, ce, out, proj_b, 512);
}